// round 6
// baseline (speedup 1.0000x reference)
#include <cuda_runtime.h>
#include <cstdint>

#define EPSF    1e-7f
#define MAXNORM (1.0f - 1e-5f)

// ---------------- W prep: f32 -> tf32 (round-to-nearest), natural [n][k] layout ----------------
__device__ uint32_t g_Wt[65536];

__global__ void wprep_kernel(const float* __restrict__ W) {
    int i = (blockIdx.x * 256 + threadIdx.x) * 4;
    float4 v = *reinterpret_cast<const float4*>(W + i);
    uint32_t o0, o1, o2, o3;
    asm("cvt.rna.tf32.f32 %0, %1;" : "=r"(o0) : "f"(v.x));
    asm("cvt.rna.tf32.f32 %0, %1;" : "=r"(o1) : "f"(v.y));
    asm("cvt.rna.tf32.f32 %0, %1;" : "=r"(o2) : "f"(v.z));
    asm("cvt.rna.tf32.f32 %0, %1;" : "=r"(o3) : "f"(v.w));
    *reinterpret_cast<uint4*>(g_Wt + i) = make_uint4(o0, o1, o2, o3);
}

// ---------------- PTX helpers ----------------
__device__ __forceinline__ uint32_t smem_u32(const void* p) {
    uint32_t a;
    asm("{ .reg .u64 t; cvta.to.shared.u64 t, %1; cvt.u32.u64 %0, t; }" : "=r"(a) : "l"(p));
    return a;
}
__device__ __forceinline__ void ldm_x4(uint32_t a, uint32_t& r0, uint32_t& r1, uint32_t& r2, uint32_t& r3) {
    asm volatile("ldmatrix.sync.aligned.m8n8.x4.shared.b16 {%0,%1,%2,%3}, [%4];"
                 : "=r"(r0), "=r"(r1), "=r"(r2), "=r"(r3) : "r"(a));
}
__device__ __forceinline__ void mma_tf32(float* c, const uint32_t* a, const uint32_t* b) {
    asm volatile("mma.sync.aligned.m16n8k8.row.col.f32.tf32.tf32.f32 "
                 "{%0,%1,%2,%3}, {%4,%5,%6,%7}, {%8,%9}, {%0,%1,%2,%3};"
                 : "+f"(c[0]), "+f"(c[1]), "+f"(c[2]), "+f"(c[3])
                 : "r"(a[0]), "r"(a[1]), "r"(a[2]), "r"(a[3]), "r"(b[0]), "r"(b[1]));
}
__device__ __forceinline__ void cp16(uint32_t dst, const void* src) {
    asm volatile("cp.async.ca.shared.global [%0], [%1], 16;" :: "r"(dst), "l"(src) : "memory");
}
#define CP_COMMIT() asm volatile("cp.async.commit_group;" ::: "memory")
#define CP_WAIT1()  asm volatile("cp.async.wait_group 1;" ::: "memory")

// ---------------- smem layout (per 64-row CTA) ----------------
#define RA_B     1040          // A row stride bytes (260 words ≡ 4 mod 32 -> conflict-free)
#define RB_B     80            // B row stride bytes (20 words ≡ 20 mod 32 -> conflict-free)
#define OFF_A    0             // 64 * 1040 = 66560
#define OFF_B    66560         // 2 stages * 256 rows * 80B = 40960
#define BSTAGE   20480
#define OFF_BIAS 107520
#define OFF_RQ   108544
#define OFF_RD   109568
#define OFF_XN2  110592
#define OFF_G1   110848
#define OFF_G2   111104
#define OFF_BN2  111360
#define SMEM_TOTAL 111616

__global__ __launch_bounds__(256, 2)
void hyp_tf32_kernel(const float* __restrict__ x, const float* __restrict__ b,
                     float* __restrict__ out, int N)
{
    extern __shared__ char smem[];
    const uint32_t sb = smem_u32(smem);
    const int tid = threadIdx.x, lane = tid & 31, wid = tid >> 5;
    const int wm = wid >> 2, wn = wid & 3;        // 2x4 warp grid, tile 32x64
    const int row0 = blockIdx.x * 64;

    // ---- B k16-stage issue: 256 threads, one n-row each (64B = 4 x cp16) ----
    auto issueB = [&](int kt, int s) {
        const uint32_t* src = g_Wt + tid * 256 + kt * 16;
        uint32_t dst = sb + OFF_B + s * BSTAGE + tid * RB_B;
        cp16(dst,      src);
        cp16(dst + 16, src + 4);
        cp16(dst + 32, src + 8);
        cp16(dst + 48, src + 12);
        CP_COMMIT();
    };
    issueB(0, 0);
    issueB(1, 1);

    // ---- bias -> smem ----
    reinterpret_cast<float*>(smem + OFF_BIAS)[tid] = b[tid];

    // ---- x prologue: 4 threads per row, 64 cols each; f32 -> tf32, ||x||^2 ----
    {
        int r = tid >> 2;
        int qc = (tid & 3) * 64;
        int gr = row0 + r; if (gr >= N) gr = N - 1;
        const float* xp = x + (size_t)gr * 256 + qc;
        float xn2p = 0.f;
        #pragma unroll
        for (int i = 0; i < 8; ++i) {
            float4 v0 = *reinterpret_cast<const float4*>(xp + i * 8);
            float4 v1 = *reinterpret_cast<const float4*>(xp + i * 8 + 4);
            xn2p += v0.x*v0.x + v0.y*v0.y + v0.z*v0.z + v0.w*v0.w
                  + v1.x*v1.x + v1.y*v1.y + v1.z*v1.z + v1.w*v1.w;
            uint32_t t0, t1, t2, t3, t4, t5, t6, t7;
            asm("cvt.rna.tf32.f32 %0, %1;" : "=r"(t0) : "f"(v0.x));
            asm("cvt.rna.tf32.f32 %0, %1;" : "=r"(t1) : "f"(v0.y));
            asm("cvt.rna.tf32.f32 %0, %1;" : "=r"(t2) : "f"(v0.z));
            asm("cvt.rna.tf32.f32 %0, %1;" : "=r"(t3) : "f"(v0.w));
            asm("cvt.rna.tf32.f32 %0, %1;" : "=r"(t4) : "f"(v1.x));
            asm("cvt.rna.tf32.f32 %0, %1;" : "=r"(t5) : "f"(v1.y));
            asm("cvt.rna.tf32.f32 %0, %1;" : "=r"(t6) : "f"(v1.z));
            asm("cvt.rna.tf32.f32 %0, %1;" : "=r"(t7) : "f"(v1.w));
            uint32_t off = (uint32_t)r * RA_B + (uint32_t)(qc + i * 8) * 4;
            *reinterpret_cast<uint4*>(smem + OFF_A + off)      = make_uint4(t0, t1, t2, t3);
            *reinterpret_cast<uint4*>(smem + OFF_A + off + 16) = make_uint4(t4, t5, t6, t7);
        }
        xn2p += __shfl_xor_sync(0xffffffffu, xn2p, 1);
        xn2p += __shfl_xor_sync(0xffffffffu, xn2p, 2);
        if (!(tid & 3)) reinterpret_cast<float*>(smem + OFF_XN2)[r] = xn2p;
    }

    // ---- accumulators: warp tile 32x64 ----
    float acc[2][8][4];
    #pragma unroll
    for (int mm = 0; mm < 2; ++mm)
        #pragma unroll
        for (int nn = 0; nn < 8; ++nn)
            #pragma unroll
            for (int q = 0; q < 4; ++q) acc[mm][nn][q] = 0.f;

    const uint32_t half16 = (lane & 16) ? 16u : 0u;
    const uint32_t aBase = sb + OFF_A + (uint32_t)(wm * 32 + (lane & 15)) * RA_B + half16;
    const uint32_t bRowOff = (uint32_t)(wn * 64 + (lane & 15)) * RB_B + half16;

    // ---- main loop: 16 ktiles of k16 (2 x k8 steps) ----
    for (int kt = 0; kt < 16; ++kt) {
        CP_WAIT1();
        __syncthreads();
        const uint32_t bStage = sb + OFF_B + (uint32_t)(kt & 1) * BSTAGE + bRowOff;
        const uint32_t aKt = aBase + (uint32_t)kt * 64;

        #pragma unroll
        for (int k8 = 0; k8 < 2; ++k8) {
            // B fragments: 4 x ldm_x4 cover 64 n (8 n8-blocks)
            uint32_t bf[8][2];
            #pragma unroll
            for (int nb = 0; nb < 4; ++nb) {
                uint32_t r0, r1, r2, r3;
                ldm_x4(bStage + (uint32_t)nb * (16 * RB_B) + (uint32_t)k8 * 32, r0, r1, r2, r3);
                bf[2*nb][0]   = r0; bf[2*nb][1]   = r2;
                bf[2*nb+1][0] = r1; bf[2*nb+1][1] = r3;
            }
            // A fragments: 2 x ldm_x4 (two 16-row blocks)
            uint32_t af[2][4];
            #pragma unroll
            for (int mm = 0; mm < 2; ++mm)
                ldm_x4(aKt + (uint32_t)k8 * 32 + (uint32_t)mm * (16 * RA_B),
                       af[mm][0], af[mm][1], af[mm][2], af[mm][3]);

            #pragma unroll
            for (int mm = 0; mm < 2; ++mm)
                #pragma unroll
                for (int nn = 0; nn < 8; ++nn)
                    mma_tf32(acc[mm][nn], af[mm], bf[nn]);
        }
        __syncthreads();
        if (kt < 14) issueB(kt + 2, kt & 1);
        else         CP_COMMIT();
    }

    // ---- epilogue: per-row reductions ----
    const float* bias = reinterpret_cast<const float*>(smem + OFF_BIAS);
    float bb[8][2];
    #pragma unroll
    for (int nn = 0; nn < 8; ++nn) {
        int col = wn * 64 + nn * 8 + (lane & 3) * 2;
        bb[nn][0] = bias[col];
        bb[nn][1] = bias[col + 1];
    }
    float* rq = reinterpret_cast<float*>(smem + OFF_RQ);
    float* rd = reinterpret_cast<float*>(smem + OFF_RD);

    #pragma unroll
    for (int mm = 0; mm < 2; ++mm)
        #pragma unroll
        for (int hf = 0; hf < 2; ++hf) {
            float q2 = 0.f, d = 0.f;
            #pragma unroll
            for (int nn = 0; nn < 8; ++nn) {
                float v0 = acc[mm][nn][hf * 2 + 0];
                float v1 = acc[mm][nn][hf * 2 + 1];
                q2 += v0 * v0 + v1 * v1;
                d  += v0 * bb[nn][0] + v1 * bb[nn][1];
            }
            q2 += __shfl_xor_sync(0xffffffffu, q2, 1);
            q2 += __shfl_xor_sync(0xffffffffu, q2, 2);
            d  += __shfl_xor_sync(0xffffffffu, d, 1);
            d  += __shfl_xor_sync(0xffffffffu, d, 2);
            if ((lane & 3) == 0) {
                int row = wm * 32 + mm * 16 + (lane >> 2) + hf * 8;
                rq[row * 4 + wn] = q2;
                rd[row * 4 + wn] = d;
            }
        }

    // ||b||^2 once per CTA (warp 0)
    if (wid == 0) {
        float v = 0.f;
        #pragma unroll
        for (int i = 0; i < 8; ++i) {
            float bv = bias[lane + i * 32];
            v += bv * bv;
        }
        #pragma unroll
        for (int off = 16; off; off >>= 1) v += __shfl_xor_sync(0xffffffffu, v, off);
        if (lane == 0) *reinterpret_cast<float*>(smem + OFF_BN2) = v;
    }
    __syncthreads();

    // ---- per-row scalar chain ----
    if (tid < 64) {
        int row = tid;
        float q2 = rq[row*4+0] + rq[row*4+1] + rq[row*4+2] + rq[row*4+3];
        float d  = rd[row*4+0] + rd[row*4+1] + rd[row*4+2] + rd[row*4+3];
        float xn2 = reinterpret_cast<float*>(smem + OFF_XN2)[row];
        float bn2 = *reinterpret_cast<float*>(smem + OFF_BN2);
        float bn  = sqrtf(bn2);

        float xn  = fmaxf(sqrtf(xn2), EPSF);
        float u   = fminf(xn, 1.0f - 1e-7f);
        float at  = 0.5f * (log1pf(u) - log1pf(-u));
        float mxn = fmaxf(sqrtf(q2), EPSF);
        float t   = tanhf(mxn / xn * at);
        t = fminf(t, MAXNORM);
        float alpha = t / mxn;
        float s  = 1.0f - t * t;
        float vn = fmaxf(s * bn, EPSF);
        float lam = 2.0f / fmaxf(s, EPSF);
        float beta = tanhf(0.5f * lam * vn) * s / vn;
        float xy = alpha * beta * d;
        float y2 = beta * beta * bn2;
        float A   = 1.0f + 2.0f * xy + y2;
        float den = fmaxf(1.0f + 2.0f * xy + (t * t) * y2, EPSF);
        float g1 = A * alpha / den;
        float g2 = s * beta  / den;
        float o2 = g1 * g1 * q2 + 2.0f * g1 * g2 * d + g2 * g2 * bn2;
        float on = fmaxf(sqrtf(o2), EPSF);
        if (on > MAXNORM) { float f = MAXNORM / on; g1 *= f; g2 *= f; }
        reinterpret_cast<float*>(smem + OFF_G1)[row] = g1;
        reinterpret_cast<float*>(smem + OFF_G2)[row] = g2;
    }
    __syncthreads();

    // ---- scaled store ----
    const float* g1s = reinterpret_cast<const float*>(smem + OFF_G1);
    const float* g2s = reinterpret_cast<const float*>(smem + OFF_G2);
    #pragma unroll
    for (int mm = 0; mm < 2; ++mm)
        #pragma unroll
        for (int hf = 0; hf < 2; ++hf) {
            int row = wm * 32 + mm * 16 + (lane >> 2) + hf * 8;
            float g1 = g1s[row], g2 = g2s[row];
            int grow = row0 + row;
            if (grow < N) {
                float* orow = out + (size_t)grow * 256;
                #pragma unroll
                for (int nn = 0; nn < 8; ++nn) {
                    float2 v;
                    v.x = g1 * acc[mm][nn][hf * 2 + 0] + g2 * bb[nn][0];
                    v.y = g1 * acc[mm][nn][hf * 2 + 1] + g2 * bb[nn][1];
                    *reinterpret_cast<float2*>(orow + wn * 64 + nn * 8 + (lane & 3) * 2) = v;
                }
            }
        }
}

extern "C" void kernel_launch(void* const* d_in, const int* in_sizes, int n_in,
                              void* d_out, int out_size) {
    const float* x = (const float*)d_in[0];
    const float* W = (const float*)d_in[1];
    const float* b = (const float*)d_in[2];
    float* out = (float*)d_out;
    int N = in_sizes[0] / 256;

    cudaFuncSetAttribute(hyp_tf32_kernel, cudaFuncAttributeMaxDynamicSharedMemorySize, SMEM_TOTAL);

    wprep_kernel<<<64, 256>>>(W);
    int grid = (N + 63) / 64;
    hyp_tf32_kernel<<<grid, 256, SMEM_TOTAL>>>(x, b, out, N);
}

// round 7
// speedup vs baseline: 2.4590x; 2.4590x over previous
#include <cuda_runtime.h>
#include <cuda_fp16.h>
#include <cstdint>

#define EPSF    1e-7f
#define MAXNORM (1.0f - 1e-5f)

// ---------------- W prep: f32 -> fp16, transposed to [k][n] ----------------
__device__ unsigned short g_WT[65536];   // [k][n] fp16

__global__ void wprep_kernel(const float* __restrict__ W) {
    __shared__ unsigned short sh[32][36];
    int bn0 = blockIdx.y * 32, bk0 = blockIdx.x * 32;
    int t = threadIdx.x;
    int r = t >> 3, c4 = (t & 7) * 4;
    float4 v = *reinterpret_cast<const float4*>(W + (bn0 + r) * 256 + bk0 + c4);
    float vv[4] = {v.x, v.y, v.z, v.w};
    #pragma unroll
    for (int j = 0; j < 4; ++j)
        sh[c4 + j][r] = __half_as_ushort(__float2half_rn(vv[j]));
    __syncthreads();
    unsigned short ho[4];
    #pragma unroll
    for (int j = 0; j < 4; ++j) ho[j] = sh[r][c4 + j];
    *reinterpret_cast<uint2*>(g_WT + (bk0 + r) * 256 + bn0 + c4) = *reinterpret_cast<uint2*>(ho);
}

// ---------------- PTX helpers ----------------
__device__ __forceinline__ uint32_t smem_u32(const void* p) {
    uint32_t a;
    asm("{ .reg .u64 t; cvta.to.shared.u64 t, %1; cvt.u32.u64 %0, t; }" : "=r"(a) : "l"(p));
    return a;
}
__device__ __forceinline__ void ldm_x4(uint32_t a, uint32_t& r0, uint32_t& r1, uint32_t& r2, uint32_t& r3) {
    asm volatile("ldmatrix.sync.aligned.m8n8.x4.shared.b16 {%0,%1,%2,%3}, [%4];"
                 : "=r"(r0), "=r"(r1), "=r"(r2), "=r"(r3) : "r"(a));
}
__device__ __forceinline__ void ldm_x4_t(uint32_t a, uint32_t& r0, uint32_t& r1, uint32_t& r2, uint32_t& r3) {
    asm volatile("ldmatrix.sync.aligned.m8n8.x4.trans.shared.b16 {%0,%1,%2,%3}, [%4];"
                 : "=r"(r0), "=r"(r1), "=r"(r2), "=r"(r3) : "r"(a));
}
__device__ __forceinline__ void mma16816(float* c, const uint32_t* a, const uint32_t* b) {
    asm volatile("mma.sync.aligned.m16n8k16.row.col.f32.f16.f16.f32 "
                 "{%0,%1,%2,%3}, {%4,%5,%6,%7}, {%8,%9}, {%0,%1,%2,%3};"
                 : "+f"(c[0]), "+f"(c[1]), "+f"(c[2]), "+f"(c[3])
                 : "r"(a[0]), "r"(a[1]), "r"(a[2]), "r"(a[3]), "r"(b[0]), "r"(b[1]));
}
__device__ __forceinline__ void cp16(uint32_t dst, const void* src) {
    asm volatile("cp.async.ca.shared.global [%0], [%1], 16;" :: "r"(dst), "l"(src) : "memory");
}
#define CP_COMMIT() asm volatile("cp.async.commit_group;" ::: "memory")
#define CP_WAIT1()  asm volatile("cp.async.wait_group 1;" ::: "memory")

// ---------------- smem layout (per 64-row CTA) ----------------
#define RA_B    528            // row stride bytes (264 fp16) - ldmatrix conflict-free
#define OFF_A   0              // 64 * 528 = 33792
#define OFF_B   33792          // 2 stages x (32 k-rows * 528B = 16896)
#define BSTAGE  16896
#define OFF_BIAS 67584
#define OFF_RQ   68608
#define OFF_RD   69632
#define OFF_XN2  70656
#define OFF_G1   70912
#define OFF_G2   71168
#define OFF_BN2  71424
#define SMEM_TOTAL 71680

__global__ __launch_bounds__(256, 2)
void hyp_f16_kernel(const float* __restrict__ x, const float* __restrict__ b,
                    float* __restrict__ out, int N)
{
    extern __shared__ char smem[];
    const uint32_t sb = smem_u32(smem);
    const int tid = threadIdx.x, lane = tid & 31, wid = tid >> 5;
    const int wm = wid >> 2, wn = wid & 3;        // 2x4 warp grid, tile 32x64
    const int row0 = blockIdx.x * 64;

    // ---- B k32-stage issue: 256 threads, 8 threads per k-row (64B each) ----
    auto issueB = [&](int kt, int s) {
        int r  = tid >> 3;                 // k-row 0..31
        int ci = tid & 7;                  // 64B chunk
        const unsigned short* src = g_WT + (kt * 32 + r) * 256 + ci * 32;
        uint32_t dst = sb + OFF_B + s * BSTAGE + r * RA_B + ci * 64;
        cp16(dst,      src);
        cp16(dst + 16, src + 8);
        cp16(dst + 32, src + 16);
        cp16(dst + 48, src + 24);
        CP_COMMIT();
    };
    issueB(0, 0);
    issueB(1, 1);

    // ---- bias -> smem ----
    reinterpret_cast<float*>(smem + OFF_BIAS)[tid] = b[tid];

    // ---- x prologue: 4 threads per row, 64 cols each; f32 -> fp16, ||x||^2 ----
    {
        int r = tid >> 2;
        int qc = (tid & 3) * 64;
        int gr = row0 + r; if (gr >= N) gr = N - 1;
        const float* xp = x + (size_t)gr * 256 + qc;
        float xn2p = 0.f;
        #pragma unroll
        for (int i = 0; i < 8; ++i) {
            float4 v0 = *reinterpret_cast<const float4*>(xp + i * 8);
            float4 v1 = *reinterpret_cast<const float4*>(xp + i * 8 + 4);
            xn2p += v0.x*v0.x + v0.y*v0.y + v0.z*v0.z + v0.w*v0.w
                  + v1.x*v1.x + v1.y*v1.y + v1.z*v1.z + v1.w*v1.w;
            uint32_t p0, p1, p2, p3;
            asm("cvt.rn.f16x2.f32 %0, %1, %2;" : "=r"(p0) : "f"(v0.y), "f"(v0.x));
            asm("cvt.rn.f16x2.f32 %0, %1, %2;" : "=r"(p1) : "f"(v0.w), "f"(v0.z));
            asm("cvt.rn.f16x2.f32 %0, %1, %2;" : "=r"(p2) : "f"(v1.y), "f"(v1.x));
            asm("cvt.rn.f16x2.f32 %0, %1, %2;" : "=r"(p3) : "f"(v1.w), "f"(v1.z));
            uint32_t off = (uint32_t)r * RA_B + (uint32_t)(qc + i * 8) * 2;
            *reinterpret_cast<uint4*>(smem + OFF_A + off) = make_uint4(p0, p1, p2, p3);
        }
        xn2p += __shfl_xor_sync(0xffffffffu, xn2p, 1);
        xn2p += __shfl_xor_sync(0xffffffffu, xn2p, 2);
        if (!(tid & 3)) reinterpret_cast<float*>(smem + OFF_XN2)[r] = xn2p;
    }

    // ---- accumulators: warp tile 32x64 ----
    float acc[2][8][4];
    #pragma unroll
    for (int mm = 0; mm < 2; ++mm)
        #pragma unroll
        for (int nn = 0; nn < 8; ++nn)
            #pragma unroll
            for (int q = 0; q < 4; ++q) acc[mm][nn][q] = 0.f;

    const int arow  = lane & 15;
    const uint32_t akoff = (lane & 16) ? 16 : 0;
    const int bkrow = lane & 15;
    const uint32_t bnoff = (lane & 16) ? 16 : 0;

    const uint32_t aBase = sb + OFF_A + (uint32_t)(wm * 32 + arow) * RA_B + akoff;
    const uint32_t bColOff = (uint32_t)(wn * 64) * 2 + bnoff;

    // ---- main loop: 8 ktiles of k32 (2 x k16 steps) ----
    for (int kt = 0; kt < 8; ++kt) {
        CP_WAIT1();
        __syncthreads();
        const uint32_t bStage = sb + OFF_B + (uint32_t)(kt & 1) * BSTAGE
                              + (uint32_t)bkrow * RA_B + bColOff;

        #pragma unroll
        for (int ks = 0; ks < 2; ++ks) {
            const uint32_t kbA = (uint32_t)(kt * 64 + ks * 32);   // bytes
            const uint32_t kbB = (uint32_t)(ks * 16) * RA_B;

            uint32_t bh[8][2];
            #pragma unroll
            for (int nb = 0; nb < 4; ++nb)
                ldm_x4_t(bStage + kbB + (uint32_t)nb * 32,
                         bh[2*nb][0], bh[2*nb][1], bh[2*nb+1][0], bh[2*nb+1][1]);
            uint32_t ah[2][4];
            #pragma unroll
            for (int mm = 0; mm < 2; ++mm)
                ldm_x4(aBase + kbA + (uint32_t)mm * (16 * RA_B),
                       ah[mm][0], ah[mm][1], ah[mm][2], ah[mm][3]);

            #pragma unroll
            for (int mm = 0; mm < 2; ++mm)
                #pragma unroll
                for (int nn = 0; nn < 8; ++nn)
                    mma16816(acc[mm][nn], ah[mm], bh[nn]);
        }
        __syncthreads();
        if (kt < 6) issueB(kt + 2, kt & 1);
        else        CP_COMMIT();
    }

    // ---- epilogue: per-row reductions ----
    const float* bias = reinterpret_cast<const float*>(smem + OFF_BIAS);
    float bb[8][2];
    #pragma unroll
    for (int nn = 0; nn < 8; ++nn) {
        int col = wn * 64 + nn * 8 + (lane & 3) * 2;
        bb[nn][0] = bias[col];
        bb[nn][1] = bias[col + 1];
    }
    float* rq = reinterpret_cast<float*>(smem + OFF_RQ);
    float* rd = reinterpret_cast<float*>(smem + OFF_RD);

    #pragma unroll
    for (int mm = 0; mm < 2; ++mm)
        #pragma unroll
        for (int hf = 0; hf < 2; ++hf) {
            float q2 = 0.f, d = 0.f;
            #pragma unroll
            for (int nn = 0; nn < 8; ++nn) {
                float v0 = acc[mm][nn][hf * 2 + 0];
                float v1 = acc[mm][nn][hf * 2 + 1];
                q2 += v0 * v0 + v1 * v1;
                d  += v0 * bb[nn][0] + v1 * bb[nn][1];
            }
            q2 += __shfl_xor_sync(0xffffffffu, q2, 1);
            q2 += __shfl_xor_sync(0xffffffffu, q2, 2);
            d  += __shfl_xor_sync(0xffffffffu, d, 1);
            d  += __shfl_xor_sync(0xffffffffu, d, 2);
            if ((lane & 3) == 0) {
                int row = wm * 32 + mm * 16 + (lane >> 2) + hf * 8;
                rq[row * 4 + wn] = q2;
                rd[row * 4 + wn] = d;
            }
        }

    // ||b||^2 once per CTA (warp 0)
    if (wid == 0) {
        float v = 0.f;
        #pragma unroll
        for (int i = 0; i < 8; ++i) {
            float bv = bias[lane + i * 32];
            v += bv * bv;
        }
        #pragma unroll
        for (int off = 16; off; off >>= 1) v += __shfl_xor_sync(0xffffffffu, v, off);
        if (lane == 0) *reinterpret_cast<float*>(smem + OFF_BN2) = v;
    }
    __syncthreads();

    // ---- per-row scalar chain ----
    if (tid < 64) {
        int row = tid;
        float q2 = rq[row*4+0] + rq[row*4+1] + rq[row*4+2] + rq[row*4+3];
        float d  = rd[row*4+0] + rd[row*4+1] + rd[row*4+2] + rd[row*4+3];
        float xn2 = reinterpret_cast<float*>(smem + OFF_XN2)[row];
        float bn2 = *reinterpret_cast<float*>(smem + OFF_BN2);
        float bn  = sqrtf(bn2);

        float xn  = fmaxf(sqrtf(xn2), EPSF);
        float u   = fminf(xn, 1.0f - 1e-7f);
        float at  = 0.5f * (log1pf(u) - log1pf(-u));
        float mxn = fmaxf(sqrtf(q2), EPSF);
        float t   = tanhf(mxn / xn * at);
        t = fminf(t, MAXNORM);
        float alpha = t / mxn;
        float s  = 1.0f - t * t;
        float vn = fmaxf(s * bn, EPSF);
        float lam = 2.0f / fmaxf(s, EPSF);
        float beta = tanhf(0.5f * lam * vn) * s / vn;
        float xy = alpha * beta * d;
        float y2 = beta * beta * bn2;
        float A   = 1.0f + 2.0f * xy + y2;
        float den = fmaxf(1.0f + 2.0f * xy + (t * t) * y2, EPSF);
        float g1 = A * alpha / den;
        float g2 = s * beta  / den;
        float o2 = g1 * g1 * q2 + 2.0f * g1 * g2 * d + g2 * g2 * bn2;
        float on = fmaxf(sqrtf(o2), EPSF);
        if (on > MAXNORM) { float f = MAXNORM / on; g1 *= f; g2 *= f; }
        reinterpret_cast<float*>(smem + OFF_G1)[row] = g1;
        reinterpret_cast<float*>(smem + OFF_G2)[row] = g2;
    }
    __syncthreads();

    // ---- scaled store ----
    const float* g1s = reinterpret_cast<const float*>(smem + OFF_G1);
    const float* g2s = reinterpret_cast<const float*>(smem + OFF_G2);
    #pragma unroll
    for (int mm = 0; mm < 2; ++mm)
        #pragma unroll
        for (int hf = 0; hf < 2; ++hf) {
            int row = wm * 32 + mm * 16 + (lane >> 2) + hf * 8;
            float g1 = g1s[row], g2 = g2s[row];
            int grow = row0 + row;
            if (grow < N) {
                float* orow = out + (size_t)grow * 256;
                #pragma unroll
                for (int nn = 0; nn < 8; ++nn) {
                    float2 v;
                    v.x = g1 * acc[mm][nn][hf * 2 + 0] + g2 * bb[nn][0];
                    v.y = g1 * acc[mm][nn][hf * 2 + 1] + g2 * bb[nn][1];
                    *reinterpret_cast<float2*>(orow + wn * 64 + nn * 8 + (lane & 3) * 2) = v;
                }
            }
        }
}

extern "C" void kernel_launch(void* const* d_in, const int* in_sizes, int n_in,
                              void* d_out, int out_size) {
    const float* x = (const float*)d_in[0];
    const float* W = (const float*)d_in[1];
    const float* b = (const float*)d_in[2];
    float* out = (float*)d_out;
    int N = in_sizes[0] / 256;

    cudaFuncSetAttribute(hyp_f16_kernel, cudaFuncAttributeMaxDynamicSharedMemorySize, SMEM_TOTAL);

    dim3 wgrid(8, 8);
    wprep_kernel<<<wgrid, 256>>>(W);
    int grid = (N + 63) / 64;
    hyp_f16_kernel<<<grid, 256, SMEM_TOTAL>>>(x, b, out, N);
}

// round 8
// speedup vs baseline: 2.5895x; 1.0531x over previous
#include <cuda_runtime.h>
#include <cuda_fp16.h>
#include <cstdint>

#define EPSF    1e-7f
#define MAXNORM (1.0f - 1e-5f)

// ---------------- W prep: f32 -> fp16, transposed to [k][n] ----------------
__device__ unsigned short g_WT[65536];   // [k][n] fp16

__global__ void wprep_kernel(const float* __restrict__ W) {
    __shared__ unsigned short sh[32][36];
    int bn0 = blockIdx.y * 32, bk0 = blockIdx.x * 32;
    int t = threadIdx.x;
    int r = t >> 3, c4 = (t & 7) * 4;
    float4 v = *reinterpret_cast<const float4*>(W + (bn0 + r) * 256 + bk0 + c4);
    float vv[4] = {v.x, v.y, v.z, v.w};
    #pragma unroll
    for (int j = 0; j < 4; ++j)
        sh[c4 + j][r] = __half_as_ushort(__float2half_rn(vv[j]));
    __syncthreads();
    unsigned short ho[4];
    #pragma unroll
    for (int j = 0; j < 4; ++j) ho[j] = sh[r][c4 + j];
    *reinterpret_cast<uint2*>(g_WT + (bk0 + r) * 256 + bn0 + c4) = *reinterpret_cast<uint2*>(ho);
}

// ---------------- PTX helpers ----------------
__device__ __forceinline__ uint32_t smem_u32(const void* p) {
    uint32_t a;
    asm("{ .reg .u64 t; cvta.to.shared.u64 t, %1; cvt.u32.u64 %0, t; }" : "=r"(a) : "l"(p));
    return a;
}
__device__ __forceinline__ void ldm_x4(uint32_t a, uint32_t& r0, uint32_t& r1, uint32_t& r2, uint32_t& r3) {
    asm volatile("ldmatrix.sync.aligned.m8n8.x4.shared.b16 {%0,%1,%2,%3}, [%4];"
                 : "=r"(r0), "=r"(r1), "=r"(r2), "=r"(r3) : "r"(a));
}
__device__ __forceinline__ void ldm_x4_t(uint32_t a, uint32_t& r0, uint32_t& r1, uint32_t& r2, uint32_t& r3) {
    asm volatile("ldmatrix.sync.aligned.m8n8.x4.trans.shared.b16 {%0,%1,%2,%3}, [%4];"
                 : "=r"(r0), "=r"(r1), "=r"(r2), "=r"(r3) : "r"(a));
}
__device__ __forceinline__ void mma16816(float* c, const uint32_t* a, const uint32_t* b) {
    asm volatile("mma.sync.aligned.m16n8k16.row.col.f32.f16.f16.f32 "
                 "{%0,%1,%2,%3}, {%4,%5,%6,%7}, {%8,%9}, {%0,%1,%2,%3};"
                 : "+f"(c[0]), "+f"(c[1]), "+f"(c[2]), "+f"(c[3])
                 : "r"(a[0]), "r"(a[1]), "r"(a[2]), "r"(a[3]), "r"(b[0]), "r"(b[1]));
}
__device__ __forceinline__ void cp16(uint32_t dst, const void* src) {
    asm volatile("cp.async.ca.shared.global [%0], [%1], 16;" :: "r"(dst), "l"(src) : "memory");
}
#define CP_COMMIT() asm volatile("cp.async.commit_group;" ::: "memory")
#define CP_WAIT3()  asm volatile("cp.async.wait_group 3;" ::: "memory")

// ---------------- smem layout (per 128-row CTA) ----------------
#define RA_B    528            // row stride bytes (264 fp16) - ldmatrix conflict-free
#define OFF_A   0              // 128 * 528 = 67584
#define OFF_B   67584          // 4 stages x (32 k-rows * 528B = 16896) = 67584
#define BSTAGE  16896
#define OFF_BIAS 135168
#define OFF_RQ   136192
#define OFF_RD   138240
#define OFF_XN2  140288
#define OFF_G1   140800
#define OFF_G2   141312
#define OFF_BN2  141824
#define SMEM_TOTAL 142336

__global__ __launch_bounds__(256, 1)
void hyp_f16_kernel(const float* __restrict__ x, const float* __restrict__ b,
                    float* __restrict__ out, int N)
{
    extern __shared__ char smem[];
    const uint32_t sb = smem_u32(smem);
    const int tid = threadIdx.x, lane = tid & 31, wid = tid >> 5;
    const int wm = wid >> 2, wn = wid & 3;        // 2x4 warp grid, tile 64x64
    const int row0 = blockIdx.x * 128;

    // ---- B k32-stage issue: 256 threads, 8 threads per k-row (64B each) ----
    auto issueB = [&](int kt, int s) {
        int r  = tid >> 3;                 // k-row 0..31
        int ci = tid & 7;                  // 64B chunk
        const unsigned short* src = g_WT + (kt * 32 + r) * 256 + ci * 32;
        uint32_t dst = sb + OFF_B + s * BSTAGE + r * RA_B + ci * 64;
        cp16(dst,      src);
        cp16(dst + 16, src + 8);
        cp16(dst + 32, src + 16);
        cp16(dst + 48, src + 24);
        CP_COMMIT();
    };
    issueB(0, 0);
    issueB(1, 1);
    issueB(2, 2);
    issueB(3, 3);

    // ---- bias -> smem ----
    reinterpret_cast<float*>(smem + OFF_BIAS)[tid] = b[tid];

    // ---- x prologue: 2 threads per row, 128 cols each; rotated chunk order
    //      (bank-group (r + j + 4h) mod 8 -> conflict-free STS.128) ----
    {
        int r = tid >> 1;
        int h = tid & 1;
        int gr = row0 + r; if (gr >= N) gr = N - 1;
        const float* xp = x + (size_t)gr * 256 + h * 128;
        float xn2p = 0.f;
        #pragma unroll
        for (int j = 0; j < 16; ++j) {
            int i = (j + 4 * h) & 15;          // chunk rotation
            float4 v0 = *reinterpret_cast<const float4*>(xp + i * 8);
            float4 v1 = *reinterpret_cast<const float4*>(xp + i * 8 + 4);
            xn2p += v0.x*v0.x + v0.y*v0.y + v0.z*v0.z + v0.w*v0.w
                  + v1.x*v1.x + v1.y*v1.y + v1.z*v1.z + v1.w*v1.w;
            uint32_t p0, p1, p2, p3;
            asm("cvt.rn.f16x2.f32 %0, %1, %2;" : "=r"(p0) : "f"(v0.y), "f"(v0.x));
            asm("cvt.rn.f16x2.f32 %0, %1, %2;" : "=r"(p1) : "f"(v0.w), "f"(v0.z));
            asm("cvt.rn.f16x2.f32 %0, %1, %2;" : "=r"(p2) : "f"(v1.y), "f"(v1.x));
            asm("cvt.rn.f16x2.f32 %0, %1, %2;" : "=r"(p3) : "f"(v1.w), "f"(v1.z));
            uint32_t off = (uint32_t)r * RA_B + (uint32_t)(h * 128 + i * 8) * 2;
            *reinterpret_cast<uint4*>(smem + OFF_A + off) = make_uint4(p0, p1, p2, p3);
        }
        xn2p += __shfl_xor_sync(0xffffffffu, xn2p, 1);
        if (!(tid & 1)) reinterpret_cast<float*>(smem + OFF_XN2)[r] = xn2p;
    }

    // ---- accumulators: warp tile 64x64 ----
    float acc[4][8][4];
    #pragma unroll
    for (int mm = 0; mm < 4; ++mm)
        #pragma unroll
        for (int nn = 0; nn < 8; ++nn)
            #pragma unroll
            for (int q = 0; q < 4; ++q) acc[mm][nn][q] = 0.f;

    const int arow  = lane & 15;
    const uint32_t akoff = (lane & 16) ? 16 : 0;
    const int bkrow = lane & 15;
    const uint32_t bnoff = (lane & 16) ? 16 : 0;

    const uint32_t aBase = sb + OFF_A + (uint32_t)(wm * 64 + arow) * RA_B + akoff;
    const uint32_t bColOff = (uint32_t)(wn * 64) * 2 + bnoff;

    // ---- main loop: 8 ktiles of k32 (2 x k16 steps), 4-stage pipeline ----
    for (int kt = 0; kt < 8; ++kt) {
        CP_WAIT3();
        __syncthreads();
        const uint32_t bStage = sb + OFF_B + (uint32_t)(kt & 3) * BSTAGE
                              + (uint32_t)bkrow * RA_B + bColOff;

        #pragma unroll
        for (int ks = 0; ks < 2; ++ks) {
            const uint32_t kbA = (uint32_t)(kt * 64 + ks * 32);   // bytes
            const uint32_t kbB = (uint32_t)(ks * 16) * RA_B;

            uint32_t bh[8][2];
            #pragma unroll
            for (int nb = 0; nb < 4; ++nb)
                ldm_x4_t(bStage + kbB + (uint32_t)nb * 32,
                         bh[2*nb][0], bh[2*nb][1], bh[2*nb+1][0], bh[2*nb+1][1]);
            uint32_t ah[4][4];
            #pragma unroll
            for (int mm = 0; mm < 4; ++mm)
                ldm_x4(aBase + kbA + (uint32_t)mm * (16 * RA_B),
                       ah[mm][0], ah[mm][1], ah[mm][2], ah[mm][3]);

            #pragma unroll
            for (int mm = 0; mm < 4; ++mm)
                #pragma unroll
                for (int nn = 0; nn < 8; ++nn)
                    mma16816(acc[mm][nn], ah[mm], bh[nn]);
        }
        __syncthreads();
        if (kt < 4) issueB(kt + 4, kt & 3);
        else        CP_COMMIT();
    }

    // ---- epilogue: per-row reductions ----
    const float* bias = reinterpret_cast<const float*>(smem + OFF_BIAS);
    float bb[8][2];
    #pragma unroll
    for (int nn = 0; nn < 8; ++nn) {
        int col = wn * 64 + nn * 8 + (lane & 3) * 2;
        bb[nn][0] = bias[col];
        bb[nn][1] = bias[col + 1];
    }
    float* rq = reinterpret_cast<float*>(smem + OFF_RQ);
    float* rd = reinterpret_cast<float*>(smem + OFF_RD);

    #pragma unroll
    for (int mm = 0; mm < 4; ++mm)
        #pragma unroll
        for (int hf = 0; hf < 2; ++hf) {
            float q2 = 0.f, d = 0.f;
            #pragma unroll
            for (int nn = 0; nn < 8; ++nn) {
                float v0 = acc[mm][nn][hf * 2 + 0];
                float v1 = acc[mm][nn][hf * 2 + 1];
                q2 += v0 * v0 + v1 * v1;
                d  += v0 * bb[nn][0] + v1 * bb[nn][1];
            }
            q2 += __shfl_xor_sync(0xffffffffu, q2, 1);
            q2 += __shfl_xor_sync(0xffffffffu, q2, 2);
            d  += __shfl_xor_sync(0xffffffffu, d, 1);
            d  += __shfl_xor_sync(0xffffffffu, d, 2);
            if ((lane & 3) == 0) {
                int row = wm * 64 + mm * 16 + (lane >> 2) + hf * 8;
                rq[row * 4 + wn] = q2;
                rd[row * 4 + wn] = d;
            }
        }

    // ||b||^2 once per CTA (warp 0)
    if (wid == 0) {
        float v = 0.f;
        #pragma unroll
        for (int i = 0; i < 8; ++i) {
            float bv = bias[lane + i * 32];
            v += bv * bv;
        }
        #pragma unroll
        for (int off = 16; off; off >>= 1) v += __shfl_xor_sync(0xffffffffu, v, off);
        if (lane == 0) *reinterpret_cast<float*>(smem + OFF_BN2) = v;
    }
    __syncthreads();

    // ---- per-row scalar chain ----
    if (tid < 128) {
        int row = tid;
        float q2 = rq[row*4+0] + rq[row*4+1] + rq[row*4+2] + rq[row*4+3];
        float d  = rd[row*4+0] + rd[row*4+1] + rd[row*4+2] + rd[row*4+3];
        float xn2 = reinterpret_cast<float*>(smem + OFF_XN2)[row];
        float bn2 = *reinterpret_cast<float*>(smem + OFF_BN2);
        float bn  = sqrtf(bn2);

        float xn  = fmaxf(sqrtf(xn2), EPSF);
        float u   = fminf(xn, 1.0f - 1e-7f);
        float at  = 0.5f * (log1pf(u) - log1pf(-u));
        float mxn = fmaxf(sqrtf(q2), EPSF);
        float t   = tanhf(mxn / xn * at);
        t = fminf(t, MAXNORM);
        float alpha = t / mxn;
        float s  = 1.0f - t * t;
        float vn = fmaxf(s * bn, EPSF);
        float lam = 2.0f / fmaxf(s, EPSF);
        float beta = tanhf(0.5f * lam * vn) * s / vn;
        float xy = alpha * beta * d;
        float y2 = beta * beta * bn2;
        float A   = 1.0f + 2.0f * xy + y2;
        float den = fmaxf(1.0f + 2.0f * xy + (t * t) * y2, EPSF);
        float g1 = A * alpha / den;
        float g2 = s * beta  / den;
        float o2 = g1 * g1 * q2 + 2.0f * g1 * g2 * d + g2 * g2 * bn2;
        float on = fmaxf(sqrtf(o2), EPSF);
        if (on > MAXNORM) { float f = MAXNORM / on; g1 *= f; g2 *= f; }
        reinterpret_cast<float*>(smem + OFF_G1)[row] = g1;
        reinterpret_cast<float*>(smem + OFF_G2)[row] = g2;
    }
    __syncthreads();

    // ---- scaled store ----
    const float* g1s = reinterpret_cast<const float*>(smem + OFF_G1);
    const float* g2s = reinterpret_cast<const float*>(smem + OFF_G2);
    #pragma unroll
    for (int mm = 0; mm < 4; ++mm)
        #pragma unroll
        for (int hf = 0; hf < 2; ++hf) {
            int row = wm * 64 + mm * 16 + (lane >> 2) + hf * 8;
            float g1 = g1s[row], g2 = g2s[row];
            int grow = row0 + row;
            if (grow < N) {
                float* orow = out + (size_t)grow * 256;
                #pragma unroll
                for (int nn = 0; nn < 8; ++nn) {
                    float2 v;
                    v.x = g1 * acc[mm][nn][hf * 2 + 0] + g2 * bb[nn][0];
                    v.y = g1 * acc[mm][nn][hf * 2 + 1] + g2 * bb[nn][1];
                    *reinterpret_cast<float2*>(orow + wn * 64 + nn * 8 + (lane & 3) * 2) = v;
                }
            }
        }
}

extern "C" void kernel_launch(void* const* d_in, const int* in_sizes, int n_in,
                              void* d_out, int out_size) {
    const float* x = (const float*)d_in[0];
    const float* W = (const float*)d_in[1];
    const float* b = (const float*)d_in[2];
    float* out = (float*)d_out;
    int N = in_sizes[0] / 256;

    cudaFuncSetAttribute(hyp_f16_kernel, cudaFuncAttributeMaxDynamicSharedMemorySize, SMEM_TOTAL);

    dim3 wgrid(8, 8);
    wprep_kernel<<<wgrid, 256>>>(W);
    int grid = (N + 127) / 128;
    hyp_f16_kernel<<<grid, 256, SMEM_TOTAL>>>(x, b, out, N);
}